// round 2
// baseline (speedup 1.0000x reference)
#include <cuda_runtime.h>
#include <cuda_bf16.h>
#include <math.h>

// ---------------------------------------------------------------------------
// Problem constants
// ---------------------------------------------------------------------------
#define BB   32          // batch
#define SS   41          // encoder seq len
#define TT   41          // decode steps
#define HH   1024        // hidden
#define VV   16384       // vocab
#define BS   (BB*SS)     // 1312

// Output packing (flat concat of reference tuple, all f32):
//   decoder_outputs [32,41,16384], h_f [1,32,1024], c_f [1,32,1024], attn [32,41,41]
#define OFF_H  ((size_t)BB*TT*VV)          // 21495808
#define OFF_C  (OFF_H + (size_t)BB*HH)     // +32768
#define OFF_A  (OFF_C + (size_t)BB*HH)     // +32768

// ---------------------------------------------------------------------------
// Device scratch (no cudaMalloc allowed)
// ---------------------------------------------------------------------------
__device__ float g_keysp[BS*HH];      // keys_proj, [bs][g] row-major
__device__ float g_encT [HH*BS];      // encoder_outputs transposed [h][bs]
__device__ float g_hT   [HH*BB];      // h, [j][b] col-major (b minor)
__device__ float g_cT   [HH*BB];      // c, [j][b]
__device__ float g_qT   [HH*BB];      // q, [g][b]
__device__ float g_Xg   [3*HH*BB];    // gates GEMM input: [x; ctx; h], [k][b]
__device__ float g_gT   [4*HH*BB];    // gates output [4096][32]
__device__ float g_bsum [4*HH];       // bih + bhh
__device__ int   g_is64;              // target dtype flag

// ---------------------------------------------------------------------------
// f32x2 packed-FMA helpers (Blackwell FFMA2)
// ---------------------------------------------------------------------------
__device__ __forceinline__ void ffma2(unsigned long long& d,
                                      unsigned long long a,
                                      unsigned long long b) {
    asm("fma.rn.f32x2 %0, %1, %2, %0;" : "+l"(d) : "l"(a), "l"(b));
}
__device__ __forceinline__ unsigned long long pack2(float lo, float hi) {
    unsigned long long r;
    asm("mov.b64 %0, {%1, %2};" : "=l"(r) : "f"(lo), "f"(hi));
    return r;
}
__device__ __forceinline__ float2 unpack2(unsigned long long v) {
    float2 f;
    asm("mov.b64 {%0, %1}, %2;" : "=f"(f.x), "=f"(f.y) : "l"(v));
    return f;
}

// ---------------------------------------------------------------------------
// GEMM: C[M, Ncols] = W[M,K] * X[K,Ncols]  (X is k-major, column = batch)
// Block tile 64 rows x 32 cols, 128 threads, BK=32.
// W may be split at K1 into (W1,ldw1) then (W2,ldw2) — used for [Wih|Whh].
// MODE 0: out[m*32 + col]            (col-major scratch)
// MODE 1: out[col*ostride + m]       (row-per-col output; logits/keys)
// ---------------------------------------------------------------------------
#define WS 68   // padded smem row stride for W tile (keeps 16B alignment)

template<int MODE>
__global__ void __launch_bounds__(128)
gemm_n32(const float* __restrict__ W1, int ldw1, int K1,
         const float* __restrict__ W2, int ldw2,
         const float* __restrict__ X, int ldx,
         const float* __restrict__ bias,
         float* __restrict__ out, long long ostride,
         int M, int K)
{
    __shared__ float w_sm[32*WS];
    __shared__ float x_sm[32*32];

    const int tid  = threadIdx.x;
    const int m0   = blockIdx.x * 64;
    const int b0   = blockIdx.y * 32;
    const int warp = tid >> 5, lane = tid & 31;
    const int warp_r = (warp >> 1) * 32;
    const int warp_b = (warp & 1) * 16;
    const int rowg = lane >> 3;          // 0..3 -> 8 rows each
    const int bg   = lane & 7;           // 0..7 -> 2 cols each
    const int r_base  = warp_r + rowg * 8;
    const int b_local = warp_b + bg * 2;

    unsigned long long acc[4][2];
#pragma unroll
    for (int i = 0; i < 4; i++) { acc[i][0] = 0ULL; acc[i][1] = 0ULL; }

    for (int k0 = 0; k0 < K; k0 += 32) {
        const float* Wb; int ld;
        if (k0 < K1) { Wb = W1 + k0;        ld = ldw1; }
        else         { Wb = W2 + (k0 - K1); ld = ldw2; }

        // stage W tile (64 rows x 32 k), transposed into [k][r]
#pragma unroll
        for (int i = 0; i < 4; i++) {
            int flat = tid + i * 128;
            int r = flat >> 3, kq = (flat & 7) * 4;
            float4 v = *reinterpret_cast<const float4*>(Wb + (size_t)(m0 + r) * ld + kq);
            w_sm[(kq + 0) * WS + r] = v.x;
            w_sm[(kq + 1) * WS + r] = v.y;
            w_sm[(kq + 2) * WS + r] = v.z;
            w_sm[(kq + 3) * WS + r] = v.w;
        }
        // stage X tile (32 k x 32 cols), already [k][col]
#pragma unroll
        for (int i = 0; i < 2; i++) {
            int flat = tid + i * 128;
            int kk = flat >> 3, bq = (flat & 7) * 4;
            float4 v = *reinterpret_cast<const float4*>(X + (size_t)(k0 + kk) * ldx + b0 + bq);
            *reinterpret_cast<float4*>(&x_sm[kk * 32 + bq]) = v;
        }
        __syncthreads();

#pragma unroll 8
        for (int kk = 0; kk < 32; kk++) {
            const float* wr = &w_sm[kk * WS + r_base];
            ulonglong2 w01 = *reinterpret_cast<const ulonglong2*>(wr);     // rows r..r+3
            ulonglong2 w23 = *reinterpret_cast<const ulonglong2*>(wr + 4); // rows r+4..r+7
            float2 xv = *reinterpret_cast<const float2*>(&x_sm[kk * 32 + b_local]);
            unsigned long long xx0 = pack2(xv.x, xv.x);
            unsigned long long xx1 = pack2(xv.y, xv.y);
            ffma2(acc[0][0], w01.x, xx0); ffma2(acc[0][1], w01.x, xx1);
            ffma2(acc[1][0], w01.y, xx0); ffma2(acc[1][1], w01.y, xx1);
            ffma2(acc[2][0], w23.x, xx0); ffma2(acc[2][1], w23.x, xx1);
            ffma2(acc[3][0], w23.y, xx0); ffma2(acc[3][1], w23.y, xx1);
        }
        __syncthreads();
    }

#pragma unroll
    for (int rp = 0; rp < 4; rp++) {
        int m = m0 + r_base + rp * 2;
        float bv0 = bias[m], bv1 = bias[m + 1];
#pragma unroll
        for (int bi = 0; bi < 2; bi++) {
            float2 v = unpack2(acc[rp][bi]);
            int col = b0 + b_local + bi;
            if (MODE == 0) {
                out[(size_t)m       * 32 + col] = v.x + bv0;
                out[(size_t)(m + 1) * 32 + col] = v.y + bv1;
            } else {
                out[(size_t)col * ostride + m]     = v.x + bv0;
                out[(size_t)col * ostride + m + 1] = v.y + bv1;
            }
        }
    }
}

// ---------------------------------------------------------------------------
// target dtype detection: if all odd 32-bit words among first 1312 are zero,
// the buffer is int64 (values < 16384 so high words are 0). 656 random int32
// values all being zero is probability ~0.
// ---------------------------------------------------------------------------
__global__ void detect_k(const int* __restrict__ tgt) {
    __shared__ int anynz;
    if (threadIdx.x == 0) anynz = 0;
    __syncthreads();
    int local = 0;
    for (int i = threadIdx.x * 2 + 1; i < BB * TT; i += 512)
        if (tgt[i] != 0) local = 1;
    if (local) atomicOr(&anynz, 1);
    __syncthreads();
    if (threadIdx.x == 0) g_is64 = (anynz == 0) ? 1 : 0;
}

// ---------------------------------------------------------------------------
// init: h0 from encoder_hidden, c0 = 0, seed h-part of Xg, bias precombine
// ---------------------------------------------------------------------------
__global__ void init_k(const float* __restrict__ ench,
                       const float* __restrict__ bih,
                       const float* __restrict__ bhh) {
    int idx = blockIdx.x * 256 + threadIdx.x;   // 32768
    int j = idx >> 5, b = idx & 31;
    float h = ench[b * HH + j];
    g_hT[idx] = h;
    g_cT[idx] = 0.f;
    g_Xg[2 * HH * BB + idx] = h;
    if (idx < 4 * HH) g_bsum[idx] = bih[idx] + bhh[idx];
}

// ---------------------------------------------------------------------------
// transpose encoder_outputs [1312][1024] -> encT [1024][1312]
// ---------------------------------------------------------------------------
__global__ void transpose_enc(const float* __restrict__ enc) {
    __shared__ float tile[32][33];
    int bs0 = blockIdx.x * 32, h0 = blockIdx.y * 32;
    int x = threadIdx.x, y = threadIdx.y;   // block (32,8)
#pragma unroll
    for (int i = 0; i < 32; i += 8)
        tile[y + i][x] = enc[(size_t)(bs0 + y + i) * HH + h0 + x];
    __syncthreads();
#pragma unroll
    for (int i = 0; i < 32; i += 8)
        g_encT[(size_t)(h0 + y + i) * BS + bs0 + x] = tile[x][y + i];
}

// ---------------------------------------------------------------------------
// Attention + embedding gather. One block per batch b.
// scores[s] = sum_h tanh(q[b,h] + keys[b,s,h]) * Vw[h] + bV
// softmax over s, ctx = sum_s w[s]*enc[b,s,:]; write x and ctx into Xg.
// ---------------------------------------------------------------------------
__global__ void __launch_bounds__(256)
attn_step(const float* __restrict__ Vw, const float* __restrict__ bVp,
          const float* __restrict__ enc, const float* __restrict__ emb,
          const void* __restrict__ tgt, float* __restrict__ out_attn, int t)
{
    __shared__ float qs[HH];
    __shared__ float vws[HH];
    __shared__ float sc[SS];
    __shared__ float wts[SS];

    const int b = blockIdx.x;
    const int tid = threadIdx.x;
    const int warp = tid >> 5, lane = tid & 31;

    for (int i = tid; i < HH; i += 256) {
        qs[i]  = g_qT[i * 32 + b];
        vws[i] = Vw[i];
    }
    __syncthreads();

    const float bVv = bVp[0];
    for (int s = warp; s < SS; s += 8) {
        const float* kp = g_keysp + ((size_t)b * SS + s) * HH;
        float acc = 0.f;
        for (int h = lane; h < HH; h += 32)
            acc += tanhf(qs[h] + kp[h]) * vws[h];
#pragma unroll
        for (int o = 16; o; o >>= 1) acc += __shfl_xor_sync(0xffffffffu, acc, o);
        if (lane == 0) sc[s] = acc + bVv;
    }
    __syncthreads();

    if (warp == 0) {
        float v0 = (lane < SS) ? sc[lane] : -3.4e38f;
        float v1 = (lane + 32 < SS) ? sc[lane + 32] : -3.4e38f;
        float m = fmaxf(v0, v1);
#pragma unroll
        for (int o = 16; o; o >>= 1) m = fmaxf(m, __shfl_xor_sync(0xffffffffu, m, o));
        float e0 = (lane < SS) ? expf(v0 - m) : 0.f;
        float e1 = (lane + 32 < SS) ? expf(v1 - m) : 0.f;
        float s = e0 + e1;
#pragma unroll
        for (int o = 16; o; o >>= 1) s += __shfl_xor_sync(0xffffffffu, s, o);
        float inv = 1.f / s;
        size_t abase = ((size_t)b * TT + t) * SS;
        if (lane < SS)      { wts[lane]      = e0 * inv; out_attn[abase + lane]      = e0 * inv; }
        if (lane + 32 < SS) { wts[lane + 32] = e1 * inv; out_attn[abase + lane + 32] = e1 * inv; }
    }
    __syncthreads();

    // ctx into Xg[HH.. 2HH)
    for (int h = tid; h < HH; h += 256) {
        float c = 0.f;
        const float* ep = enc + (size_t)b * SS * HH + h;
#pragma unroll 1
        for (int s = 0; s < SS; s++)
            c += wts[s] * ep[(size_t)s * HH];
        g_Xg[(size_t)(HH + h) * 32 + b] = c;
    }

    // embedding x into Xg[0..HH)
    long long tok;
    if (t == 0) tok = 0;
    else if (g_is64) tok = ((const long long*)tgt)[(size_t)b * TT + (t - 1)];
    else             tok = (long long)((const int*)tgt)[(size_t)b * TT + (t - 1)];
    const float* er = emb + (size_t)tok * HH;
    for (int h = tid; h < HH; h += 256)
        g_Xg[(size_t)h * 32 + b] = er[h];
}

// ---------------------------------------------------------------------------
// LSTM pointwise: gates in g_gT [4096][32] (i,f,g,o blocks of 1024 rows)
// ---------------------------------------------------------------------------
__device__ __forceinline__ float sigm(float x) { return 1.f / (1.f + expf(-x)); }

__global__ void __launch_bounds__(256) lstm_k() {
    int idx = blockIdx.x * 256 + threadIdx.x;   // 32768 = [j][b]
    float ig = sigm (g_gT[idx]);
    float fg = sigm (g_gT[1 * HH * BB + idx]);
    float gg = tanhf(g_gT[2 * HH * BB + idx]);
    float og = sigm (g_gT[3 * HH * BB + idx]);
    float c = fg * g_cT[idx] + ig * gg;
    float h = og * tanhf(c);
    g_cT[idx] = c;
    g_hT[idx] = h;
    g_Xg[2 * HH * BB + idx] = h;   // h-part of next step's gates input
}

// ---------------------------------------------------------------------------
// final h/c transpose into output
// ---------------------------------------------------------------------------
__global__ void final_hc(float* __restrict__ oh, float* __restrict__ oc) {
    int idx = blockIdx.x * 256 + threadIdx.x;   // 32768
    int b = idx >> 10, j = idx & 1023;
    oh[idx] = g_hT[j * 32 + b];
    oc[idx] = g_cT[j * 32 + b];
}

// ---------------------------------------------------------------------------
// log_softmax in place over each [16384] row of decoder outputs
// ---------------------------------------------------------------------------
__global__ void __launch_bounds__(256) logsoftmax_rows(float* __restrict__ out) {
    float* row = out + (size_t)blockIdx.x * VV;
    __shared__ float red1[8];
    __shared__ float red2[8];
    const int tid = threadIdx.x;
    const int warp = tid >> 5, lane = tid & 31;

    float m = -3.4e38f;
    for (int i = tid; i < VV; i += 256) m = fmaxf(m, row[i]);
#pragma unroll
    for (int o = 16; o; o >>= 1) m = fmaxf(m, __shfl_xor_sync(0xffffffffu, m, o));
    if (lane == 0) red1[warp] = m;
    __syncthreads();
    m = red1[0];
#pragma unroll
    for (int i = 1; i < 8; i++) m = fmaxf(m, red1[i]);

    float s = 0.f;
    for (int i = tid; i < VV; i += 256) s += expf(row[i] - m);
#pragma unroll
    for (int o = 16; o; o >>= 1) s += __shfl_xor_sync(0xffffffffu, s, o);
    if (lane == 0) red2[warp] = s;
    __syncthreads();
    s = red2[0];
#pragma unroll
    for (int i = 1; i < 8; i++) s += red2[i];
    float shift = m + logf(s);

    for (int i = tid; i < VV; i += 256) row[i] = row[i] - shift;
}

// ---------------------------------------------------------------------------
// host launcher
// ---------------------------------------------------------------------------
extern "C" void kernel_launch(void* const* d_in, const int* in_sizes, int n_in,
                              void* d_out, int out_size)
{
    const float* enc   = (const float*)d_in[0];
    const float* ench  = (const float*)d_in[1];
    const void*  tgt   = d_in[2];
    const float* emb   = (const float*)d_in[3];
    const float* Wq    = (const float*)d_in[4];
    const float* bq    = (const float*)d_in[5];
    const float* Wk    = (const float*)d_in[6];
    const float* bk    = (const float*)d_in[7];
    const float* Vw    = (const float*)d_in[8];
    const float* bV    = (const float*)d_in[9];
    const float* Wih   = (const float*)d_in[10];
    const float* Whh   = (const float*)d_in[11];
    const float* bih   = (const float*)d_in[12];
    const float* bhh   = (const float*)d_in[13];
    const float* Wout  = (const float*)d_in[14];
    const float* bout  = (const float*)d_in[15];
    float* out = (float*)d_out;

    float *keysp, *encT, *hT, *Xg, *gT, *qT, *bsum;
    cudaGetSymbolAddress((void**)&keysp, g_keysp);
    cudaGetSymbolAddress((void**)&encT,  g_encT);
    cudaGetSymbolAddress((void**)&hT,    g_hT);
    cudaGetSymbolAddress((void**)&Xg,    g_Xg);
    cudaGetSymbolAddress((void**)&gT,    g_gT);
    cudaGetSymbolAddress((void**)&qT,    g_qT);
    cudaGetSymbolAddress((void**)&bsum,  g_bsum);

    detect_k<<<1, 256>>>((const int*)tgt);
    init_k<<<128, 256>>>(ench, bih, bhh);
    transpose_enc<<<dim3(BS / 32, HH / 32), dim3(32, 8)>>>(enc);

    // keys_proj[bs][g] = enc[bs] . Wk[g] + bk[g]
    gemm_n32<1><<<dim3(HH / 64, BS / 32), 128>>>(
        Wk, HH, HH, nullptr, 0, encT, BS, bk, keysp, (long long)HH, HH, HH);

    for (int t = 0; t < TT; t++) {
        // q = Wq . h + bq   -> qT [1024][32]
        gemm_n32<0><<<dim3(HH / 64, 1), 128>>>(
            Wq, HH, HH, nullptr, 0, hT, 32, bq, qT, 0, HH, HH);

        attn_step<<<BB, 256>>>(Vw, bV, enc, emb, tgt, out + OFF_A, t);

        // gates = [Wih | Whh] . [x; ctx; h] + (bih + bhh)
        gemm_n32<0><<<dim3(4 * HH / 64, 1), 128>>>(
            Wih, 2 * HH, 2 * HH, Whh, HH, Xg, 32, bsum, gT, 0, 4 * HH, 3 * HH);

        lstm_k<<<128, 256>>>();

        // logits = Wout . h_new + bout  -> directly into out[b][t][:]
        gemm_n32<1><<<dim3(VV / 64, 1), 128>>>(
            Wout, HH, HH, nullptr, 0, hT, 32, bout,
            out + (size_t)t * VV, (long long)TT * VV, VV, HH);
    }

    final_hc<<<128, 256>>>(out + OFF_H, out + OFF_C);
    logsoftmax_rows<<<BB * TT, 256>>>(out);
}

// round 4
// speedup vs baseline: 1.7984x; 1.7984x over previous
#include <cuda_runtime.h>
#include <cuda_bf16.h>
#include <math.h>

// ---------------------------------------------------------------------------
// Problem constants
// ---------------------------------------------------------------------------
#define BB   32          // batch
#define SS   41          // encoder seq len
#define TT   41          // decode steps
#define HH   1024        // hidden
#define VV   16384       // vocab
#define BS   (BB*SS)     // 1312

#define OFF_H  ((size_t)BB*TT*VV)
#define OFF_C  (OFF_H + (size_t)BB*HH)
#define OFF_A  (OFF_C + (size_t)BB*HH)

// ---------------------------------------------------------------------------
// Device scratch
// ---------------------------------------------------------------------------
__device__ float g_keysp[BS*HH];      // keys_proj, [bs][g]
__device__ float g_encT [HH*BS];      // encoder_outputs transposed [h][bs]
__device__ float g_hT   [HH*BB];      // h, [j][b]
__device__ float g_cT   [HH*BB];      // c, [j][b]
__device__ float g_Xg   [3*HH*BB];    // gates input: [x; ctx; h], [k][b]
__device__ float g_qp   [4*HH*BB];    // q partials  [4][1024][32]
__device__ float g_gp   [4*4*HH*BB];  // gate partials [4][4096][32]
__device__ float g_bsum [4*HH];       // bih + bhh
__device__ int   g_is64;

// ---------------------------------------------------------------------------
// f32x2 packed-FMA helpers
// ---------------------------------------------------------------------------
__device__ __forceinline__ void ffma2(unsigned long long& d,
                                      unsigned long long a,
                                      unsigned long long b) {
    asm("fma.rn.f32x2 %0, %1, %2, %0;" : "+l"(d) : "l"(a), "l"(b));
}
__device__ __forceinline__ unsigned long long pack2(float lo, float hi) {
    unsigned long long r;
    asm("mov.b64 %0, {%1, %2};" : "=l"(r) : "f"(lo), "f"(hi));
    return r;
}
__device__ __forceinline__ float2 unpack2(unsigned long long v) {
    float2 f;
    asm("mov.b64 {%0, %1}, %2;" : "=f"(f.x), "=f"(f.y) : "l"(v));
    return f;
}

// ---------------------------------------------------------------------------
// GEMM: C[M,32] (+ optionally more col blocks) = W[M,K] * X[K,N]
//   X is k-major: X[k*ldx + col].
//   BM=128, BN=32, BK=16, 128 threads, thread tile 8 rows x 4 cols.
//   Double-buffered smem, register prefetch, 1 sync per k-tile.
//   W optionally split at K1 into (W1,ldw1)/(W2,ldw2)  (for [Wih|Whh]).
//   Split-K via blockIdx.z (chunk kz covers [kz*Kchunk, (kz+1)*Kchunk)).
// MODE 1: final:   out[col*ostride + m] = acc + bias[m]   (coalesced via smem)
// MODE 2: partial: out[kz*M*32 + m*32 + col] = acc        (no bias)
// ---------------------------------------------------------------------------
#define BK 16
#define WSTR 132   // padded smem stride for W tile rows (16B-aligned)

template<int MODE>
__global__ void __launch_bounds__(128)
gemm128(const float* __restrict__ W1, int ldw1, int K1,
        const float* __restrict__ W2, int ldw2,
        const float* __restrict__ X, int ldx,
        const float* __restrict__ bias,
        float* __restrict__ out, long long ostride,
        int M, int Kchunk)
{
    __shared__ float w_sm[2][BK*WSTR];   // [k][r], 2112 floats each
    __shared__ float x_sm[2][BK*32];

    const int tid = threadIdx.x;
    const int m0  = blockIdx.x * 128;
    const int b0  = blockIdx.y * 32;
    const int kz  = blockIdx.z;
    const int kbase = kz * Kchunk;

    const int ty = tid >> 3;           // 0..15
    const int tx = tid & 7;            // 0..7
    const int r0 = ty * 8;             // 8 rows per thread
    const int c0 = tx * 4;             // 4 cols per thread

    // loader mapping
    const int lr = tid >> 2;           // 0..31 (row within 32-row group)
    const int lk = (tid & 3) * 4;      // k quad
    const int xk = tid >> 3;           // 0..15
    const int xc = (tid & 7) * 4;

    unsigned long long acc[4][4];
#pragma unroll
    for (int i = 0; i < 4; i++)
#pragma unroll
        for (int j = 0; j < 4; j++) acc[i][j] = 0ULL;

    float4 wreg[4];
    float4 xreg;

    const int ntiles = Kchunk / BK;

    // ---- prologue load tile 0
    {
        int k0 = kbase;
        const float* Wb; int ld;
        if (k0 < K1) { Wb = W1 + k0; ld = ldw1; } else { Wb = W2 + (k0 - K1); ld = ldw2; }
#pragma unroll
        for (int i = 0; i < 4; i++)
            wreg[i] = *reinterpret_cast<const float4*>(Wb + (size_t)(m0 + lr + i * 32) * ld + lk);
        xreg = *reinterpret_cast<const float4*>(X + (size_t)(k0 + xk) * ldx + b0 + xc);
    }
    {
#pragma unroll
        for (int i = 0; i < 4; i++) {
            int r = lr + i * 32;
            w_sm[0][(lk + 0) * WSTR + r] = wreg[i].x;
            w_sm[0][(lk + 1) * WSTR + r] = wreg[i].y;
            w_sm[0][(lk + 2) * WSTR + r] = wreg[i].z;
            w_sm[0][(lk + 3) * WSTR + r] = wreg[i].w;
        }
        *reinterpret_cast<float4*>(&x_sm[0][xk * 32 + xc]) = xreg;
    }
    __syncthreads();

    for (int t = 0; t < ntiles; t++) {
        // prefetch next tile into registers (LDG latency hidden by compute)
        if (t + 1 < ntiles) {
            int k0 = kbase + (t + 1) * BK;
            const float* Wb; int ld;
            if (k0 < K1) { Wb = W1 + k0; ld = ldw1; } else { Wb = W2 + (k0 - K1); ld = ldw2; }
#pragma unroll
            for (int i = 0; i < 4; i++)
                wreg[i] = *reinterpret_cast<const float4*>(Wb + (size_t)(m0 + lr + i * 32) * ld + lk);
            xreg = *reinterpret_cast<const float4*>(X + (size_t)(k0 + xk) * ldx + b0 + xc);
        }

        // compute on buffer t&1
        {
            const float* wb = w_sm[t & 1];
            const float* xb = x_sm[t & 1];
#pragma unroll
            for (int kk = 0; kk < BK; kk++) {
                const float* wr = wb + kk * WSTR + r0;
                ulonglong2 wa = *reinterpret_cast<const ulonglong2*>(wr);      // rows r0..r0+3
                ulonglong2 wbv = *reinterpret_cast<const ulonglong2*>(wr + 4); // rows r0+4..r0+7
                float4 xv = *reinterpret_cast<const float4*>(xb + kk * 32 + c0);
                unsigned long long xx0 = pack2(xv.x, xv.x);
                unsigned long long xx1 = pack2(xv.y, xv.y);
                unsigned long long xx2 = pack2(xv.z, xv.z);
                unsigned long long xx3 = pack2(xv.w, xv.w);
                ffma2(acc[0][0], wa.x, xx0);  ffma2(acc[0][1], wa.x, xx1);
                ffma2(acc[0][2], wa.x, xx2);  ffma2(acc[0][3], wa.x, xx3);
                ffma2(acc[1][0], wa.y, xx0);  ffma2(acc[1][1], wa.y, xx1);
                ffma2(acc[1][2], wa.y, xx2);  ffma2(acc[1][3], wa.y, xx3);
                ffma2(acc[2][0], wbv.x, xx0); ffma2(acc[2][1], wbv.x, xx1);
                ffma2(acc[2][2], wbv.x, xx2); ffma2(acc[2][3], wbv.x, xx3);
                ffma2(acc[3][0], wbv.y, xx0); ffma2(acc[3][1], wbv.y, xx1);
                ffma2(acc[3][2], wbv.y, xx2); ffma2(acc[3][3], wbv.y, xx3);
            }
        }

        // store prefetched tile into other buffer
        if (t + 1 < ntiles) {
            int buf = (t + 1) & 1;
#pragma unroll
            for (int i = 0; i < 4; i++) {
                int r = lr + i * 32;
                w_sm[buf][(lk + 0) * WSTR + r] = wreg[i].x;
                w_sm[buf][(lk + 1) * WSTR + r] = wreg[i].y;
                w_sm[buf][(lk + 2) * WSTR + r] = wreg[i].z;
                w_sm[buf][(lk + 3) * WSTR + r] = wreg[i].w;
            }
            *reinterpret_cast<float4*>(&x_sm[buf][xk * 32 + xc]) = xreg;
        }
        __syncthreads();
    }

    if (MODE == 1) {
        // stage C tile [col][m] into smem (stride 132), then coalesced stores
        float* c = &w_sm[0][0];   // 4224 floats available = 32*132
#pragma unroll
        for (int rp = 0; rp < 4; rp++) {
            int m = r0 + rp * 2;
            float bv0 = bias[m0 + m], bv1 = bias[m0 + m + 1];
#pragma unroll
            for (int cj = 0; cj < 4; cj++) {
                float2 v = unpack2(acc[rp][cj]);
                int col = c0 + cj;
                c[col * 132 + m]     = v.x + bv0;
                c[col * 132 + m + 1] = v.y + bv1;
            }
        }
        __syncthreads();
        int col = tid >> 2, seg = (tid & 3) * 32;
        float* op = out + (size_t)(b0 + col) * ostride + m0 + seg;
        const float* cp = c + col * 132 + seg;
#pragma unroll
        for (int i = 0; i < 8; i++)
            *reinterpret_cast<float4*>(op + i * 4) =
                *reinterpret_cast<const float4*>(cp + i * 4);
    } else {
        // partial: out[kz*M*32 + m*32 + col]
        float* p = out + (size_t)kz * M * 32;
#pragma unroll
        for (int rp = 0; rp < 4; rp++) {
            int m = m0 + r0 + rp * 2;
#pragma unroll
            for (int cj = 0; cj < 4; cj++) {
                float2 v = unpack2(acc[rp][cj]);
                int col = c0 + cj;
                p[(size_t)m * 32 + col]       = v.x;
                p[(size_t)(m + 1) * 32 + col] = v.y;
            }
        }
    }
}

// ---------------------------------------------------------------------------
// target dtype detection
// ---------------------------------------------------------------------------
__global__ void detect_k(const int* __restrict__ tgt) {
    __shared__ int anynz;
    if (threadIdx.x == 0) anynz = 0;
    __syncthreads();
    int local = 0;
    for (int i = threadIdx.x * 2 + 1; i < BB * TT; i += 512)
        if (tgt[i] != 0) local = 1;
    if (local) atomicOr(&anynz, 1);
    __syncthreads();
    if (threadIdx.x == 0) g_is64 = (anynz == 0) ? 1 : 0;
}

// ---------------------------------------------------------------------------
// init
// ---------------------------------------------------------------------------
__global__ void init_k(const float* __restrict__ ench,
                       const float* __restrict__ bih,
                       const float* __restrict__ bhh) {
    int idx = blockIdx.x * 256 + threadIdx.x;   // 32768
    int j = idx >> 5, b = idx & 31;
    float h = ench[b * HH + j];
    g_hT[idx] = h;
    g_cT[idx] = 0.f;
    g_Xg[2 * HH * BB + idx] = h;
    if (idx < 4 * HH) g_bsum[idx] = bih[idx] + bhh[idx];
}

// ---------------------------------------------------------------------------
// transpose encoder_outputs [1312][1024] -> encT [1024][1312]
// ---------------------------------------------------------------------------
__global__ void transpose_enc(const float* __restrict__ enc) {
    __shared__ float tile[32][33];
    int bs0 = blockIdx.x * 32, h0 = blockIdx.y * 32;
    int x = threadIdx.x, y = threadIdx.y;
#pragma unroll
    for (int i = 0; i < 32; i += 8)
        tile[y + i][x] = enc[(size_t)(bs0 + y + i) * HH + h0 + x];
    __syncthreads();
#pragma unroll
    for (int i = 0; i < 32; i += 8)
        g_encT[(size_t)(h0 + y + i) * BS + bs0 + x] = tile[x][y + i];
}

// ---------------------------------------------------------------------------
// Attention + q-partial combine + embedding gather. One block per batch b.
// ---------------------------------------------------------------------------
__global__ void __launch_bounds__(256)
attn_step(const float* __restrict__ Vw, const float* __restrict__ bVp,
          const float* __restrict__ bq,
          const float* __restrict__ enc, const float* __restrict__ emb,
          const void* __restrict__ tgt, float* __restrict__ out_attn, int t)
{
    __shared__ float qs[HH];
    __shared__ float vws[HH];
    __shared__ float sc[SS];
    __shared__ float wts[SS];

    const int b = blockIdx.x;
    const int tid = threadIdx.x;
    const int warp = tid >> 5, lane = tid & 31;

    for (int i = tid; i < HH; i += 256) {
        float q = bq[i];
#pragma unroll
        for (int s = 0; s < 4; s++) q += g_qp[s * (HH * BB) + i * 32 + b];
        qs[i]  = q;
        vws[i] = Vw[i];
    }
    __syncthreads();

    const float bVv = bVp[0];
    for (int s = warp; s < SS; s += 8) {
        const float* kp = g_keysp + ((size_t)b * SS + s) * HH;
        float acc = 0.f;
        for (int h = lane; h < HH; h += 32)
            acc += tanhf(qs[h] + kp[h]) * vws[h];
#pragma unroll
        for (int o = 16; o; o >>= 1) acc += __shfl_xor_sync(0xffffffffu, acc, o);
        if (lane == 0) sc[s] = acc + bVv;
    }
    __syncthreads();

    if (warp == 0) {
        float v0 = (lane < SS) ? sc[lane] : -3.4e38f;
        float v1 = (lane + 32 < SS) ? sc[lane + 32] : -3.4e38f;
        float m = fmaxf(v0, v1);
#pragma unroll
        for (int o = 16; o; o >>= 1) m = fmaxf(m, __shfl_xor_sync(0xffffffffu, m, o));
        float e0 = (lane < SS) ? expf(v0 - m) : 0.f;
        float e1 = (lane + 32 < SS) ? expf(v1 - m) : 0.f;
        float s = e0 + e1;
#pragma unroll
        for (int o = 16; o; o >>= 1) s += __shfl_xor_sync(0xffffffffu, s, o);
        float inv = 1.f / s;
        size_t abase = ((size_t)b * TT + t) * SS;
        if (lane < SS)      { wts[lane]      = e0 * inv; out_attn[abase + lane]      = e0 * inv; }
        if (lane + 32 < SS) { wts[lane + 32] = e1 * inv; out_attn[abase + lane + 32] = e1 * inv; }
    }
    __syncthreads();

    for (int h = tid; h < HH; h += 256) {
        float c = 0.f;
        const float* ep = enc + (size_t)b * SS * HH + h;
#pragma unroll 1
        for (int s = 0; s < SS; s++)
            c += wts[s] * ep[(size_t)s * HH];
        g_Xg[(size_t)(HH + h) * 32 + b] = c;
    }

    long long tok;
    if (t == 0) tok = 0;
    else if (g_is64) tok = ((const long long*)tgt)[(size_t)b * TT + (t - 1)];
    else             tok = (long long)((const int*)tgt)[(size_t)b * TT + (t - 1)];
    const float* er = emb + (size_t)tok * HH;
    for (int h = tid; h < HH; h += 256)
        g_Xg[(size_t)h * 32 + b] = er[h];
}

// ---------------------------------------------------------------------------
// LSTM pointwise fused with split-K combine of gate partials
// g_gp layout: [chunk s][row][b], rows: i=0..1023, f=1024.., g=2048.., o=3072..
// ---------------------------------------------------------------------------
__device__ __forceinline__ float sigm(float x) { return 1.f / (1.f + expf(-x)); }

__global__ void __launch_bounds__(256) lstm_comb() {
    int idx = blockIdx.x * 256 + threadIdx.x;   // 32768 = j*32 + b
    int j = idx >> 5;
    float gi = g_bsum[j], gf = g_bsum[HH + j], gg = g_bsum[2 * HH + j], go = g_bsum[3 * HH + j];
#pragma unroll
    for (int s = 0; s < 4; s++) {
        const float* p = g_gp + (size_t)s * (4 * HH * BB);
        gi += p[idx];
        gf += p[1 * HH * BB + idx];
        gg += p[2 * HH * BB + idx];
        go += p[3 * HH * BB + idx];
    }
    float ig = sigm(gi), fg = sigm(gf), ggt = tanhf(gg), og = sigm(go);
    float c = fg * g_cT[idx] + ig * ggt;
    float h = og * tanhf(c);
    g_cT[idx] = c;
    g_hT[idx] = h;
    g_Xg[2 * HH * BB + idx] = h;
}

// ---------------------------------------------------------------------------
// final h/c transpose into output
// ---------------------------------------------------------------------------
__global__ void final_hc(float* __restrict__ oh, float* __restrict__ oc) {
    int idx = blockIdx.x * 256 + threadIdx.x;
    int b = idx >> 10, j = idx & 1023;
    oh[idx] = g_hT[j * 32 + b];
    oc[idx] = g_cT[j * 32 + b];
}

// ---------------------------------------------------------------------------
// log_softmax in place over each [16384] row
// ---------------------------------------------------------------------------
__global__ void __launch_bounds__(256) logsoftmax_rows(float* __restrict__ out) {
    float* row = out + (size_t)blockIdx.x * VV;
    __shared__ float red1[8];
    __shared__ float red2[8];
    const int tid = threadIdx.x;
    const int warp = tid >> 5, lane = tid & 31;

    float m = -3.4e38f;
    for (int i = tid; i < VV; i += 256) m = fmaxf(m, row[i]);
#pragma unroll
    for (int o = 16; o; o >>= 1) m = fmaxf(m, __shfl_xor_sync(0xffffffffu, m, o));
    if (lane == 0) red1[warp] = m;
    __syncthreads();
    m = red1[0];
#pragma unroll
    for (int i = 1; i < 8; i++) m = fmaxf(m, red1[i]);

    float s = 0.f;
    for (int i = tid; i < VV; i += 256) s += expf(row[i] - m);
#pragma unroll
    for (int o = 16; o; o >>= 1) s += __shfl_xor_sync(0xffffffffu, s, o);
    if (lane == 0) red2[warp] = s;
    __syncthreads();
    s = red2[0];
#pragma unroll
    for (int i = 1; i < 8; i++) s += red2[i];
    float shift = m + logf(s);

    for (int i = tid; i < VV; i += 256) row[i] = row[i] - shift;
}

// ---------------------------------------------------------------------------
// host launcher
// ---------------------------------------------------------------------------
extern "C" void kernel_launch(void* const* d_in, const int* in_sizes, int n_in,
                              void* d_out, int out_size)
{
    const float* enc   = (const float*)d_in[0];
    const float* ench  = (const float*)d_in[1];
    const void*  tgt   = d_in[2];
    const float* emb   = (const float*)d_in[3];
    const float* Wq    = (const float*)d_in[4];
    const float* bq    = (const float*)d_in[5];
    const float* Wk    = (const float*)d_in[6];
    const float* bk    = (const float*)d_in[7];
    const float* Vw    = (const float*)d_in[8];
    const float* bV    = (const float*)d_in[9];
    const float* Wih   = (const float*)d_in[10];
    const float* Whh   = (const float*)d_in[11];
    const float* bih   = (const float*)d_in[12];
    const float* bhh   = (const float*)d_in[13];
    const float* Wout  = (const float*)d_in[14];
    const float* bout  = (const float*)d_in[15];
    float* out = (float*)d_out;

    float *keysp, *encT, *hT, *Xg, *qp, *gp;
    cudaGetSymbolAddress((void**)&keysp, g_keysp);
    cudaGetSymbolAddress((void**)&encT,  g_encT);
    cudaGetSymbolAddress((void**)&hT,    g_hT);
    cudaGetSymbolAddress((void**)&Xg,    g_Xg);
    cudaGetSymbolAddress((void**)&qp,    g_qp);
    cudaGetSymbolAddress((void**)&gp,    g_gp);

    const int BIGK = 1 << 28;

    detect_k<<<1, 256>>>((const int*)tgt);
    init_k<<<128, 256>>>(ench, bih, bhh);
    transpose_enc<<<dim3(BS / 32, HH / 32), dim3(32, 8)>>>(enc);

    // keys_proj[bs][g] = enc[bs].Wk[g] + bk  (MODE1, cols = 1312 in 41 blocks)
    gemm128<1><<<dim3(HH / 128, 41, 1), 128>>>(
        Wk, HH, BIGK, nullptr, 0, encT, BS, bk, keysp, (long long)HH, HH, HH);

    for (int t = 0; t < TT; t++) {
        // q partials: Wq[1024,1024] * hT  (split-K 4)
        gemm128<2><<<dim3(HH / 128, 1, 4), 128>>>(
            Wq, HH, BIGK, nullptr, 0, hT, 32, nullptr, qp, 0, HH, HH / 4);

        attn_step<<<BB, 256>>>(Vw, bV, bq, enc, emb, tgt, out + OFF_A, t);

        // gate partials: [Wih|Whh][4096,3072] * Xg  (split-K 4, chunks of 768)
        gemm128<2><<<dim3(4 * HH / 128, 1, 4), 128>>>(
            Wih, 2 * HH, 2 * HH, Whh, HH, Xg, 32, nullptr, gp, 0, 4 * HH, 3 * HH / 4);

        lstm_comb<<<128, 256>>>();

        // logits: Wout[16384,1024] * hT -> out[b][t][:]  (MODE1)
        gemm128<1><<<dim3(VV / 128, 1, 1), 128>>>(
            Wout, HH, BIGK, nullptr, 0, hT, 32, bout,
            out + (size_t)t * VV, (long long)TT * VV, VV, HH);
    }

    final_hc<<<128, 256>>>(out + OFF_H, out + OFF_C);
    logsoftmax_rows<<<BB * TT, 256>>>(out);
}

// round 5
// speedup vs baseline: 3.9319x; 2.1863x over previous
#include <cuda_runtime.h>
#include <cuda_bf16.h>
#include <math.h>

// ---------------------------------------------------------------------------
// Problem constants
// ---------------------------------------------------------------------------
#define BB   32          // batch
#define SS   41          // encoder seq len
#define TT   41          // decode steps
#define HH   1024        // hidden
#define VV   16384       // vocab
#define BS   (BB*SS)     // 1312 = TT*BB too

#define OFF_H  ((size_t)BB*TT*VV)
#define OFF_C  (OFF_H + (size_t)BB*HH)
#define OFF_A  (OFF_C + (size_t)BB*HH)

#define NSPL 8           // split-K factor for in-loop GEMMs

// ---------------------------------------------------------------------------
// Device scratch
// ---------------------------------------------------------------------------
__device__ float g_keysp[BS*HH];        // keys_proj, [bs][g]
__device__ float g_encT [HH*BS];        // encoder_outputs transposed [h][bs]
__device__ float g_hT   [HH*BB];        // h, [j][b]
__device__ float g_cT   [HH*BB];        // c, [j][b]
__device__ float g_Xg   [2*HH*BB];      // gates input: [ctx; h], [k][b]
__device__ float g_qp   [NSPL*HH*BB];   // q partials  [8][1024][32]
__device__ float g_gp   [NSPL*4*HH*BB]; // gate partials [8][4096][32]
__device__ float g_bsum [4*HH];         // bih + bhh
__device__ float g_Xall [HH*BS];        // embedded tokens, [k][t*32+b]
__device__ float g_gx   [TT*4*HH*BB];   // precomputed Wih_x * x, [t][m][b]
__device__ float g_Hall [HH*BS];        // all h states, [j][t*32+b]
__device__ int   g_is64;

// ---------------------------------------------------------------------------
// f32x2 packed-FMA helpers
// ---------------------------------------------------------------------------
__device__ __forceinline__ void ffma2(unsigned long long& d,
                                      unsigned long long a,
                                      unsigned long long b) {
    asm("fma.rn.f32x2 %0, %1, %2, %0;" : "+l"(d) : "l"(a), "l"(b));
}
__device__ __forceinline__ unsigned long long pack2(float lo, float hi) {
    unsigned long long r;
    asm("mov.b64 %0, {%1, %2};" : "=l"(r) : "f"(lo), "f"(hi));
    return r;
}
__device__ __forceinline__ float2 unpack2(unsigned long long v) {
    float2 f;
    asm("mov.b64 {%0, %1}, %2;" : "=f"(f.x), "=f"(f.y) : "l"(v));
    return f;
}

// ---------------------------------------------------------------------------
// GEMM: C[M,*] = W[M,K] * X[K,N],  X k-major (X[k*ldx + col]).
//   BM=128, BN=32, BK=16, 128 threads, thread tile 8 rows x 4 cols.
//   Double-buffered smem, register prefetch.
//   W split at K1 into (W1,ldw1)/(W2,ldw2).
//   Split-K via blockIdx.z.
// MODE 1: out[col*ostride + m] + bias      (smem-staged coalesced)
// MODE 2: out[kz*M*32 + m*32 + col]        (split-K partial, no bias)
// MODE 3: out[(col>>5)*M*32 + m*32 + (col&31)]   (x-precompute, no bias)
// MODE 4: out[((col&31)*TT + (col>>5))*VV + m] + bias  (deferred logits)
// ---------------------------------------------------------------------------
#define BK 16
#define WSTR 132

template<int MODE>
__global__ void __launch_bounds__(128)
gemm128(const float* __restrict__ W1, int ldw1, int K1,
        const float* __restrict__ W2, int ldw2,
        const float* __restrict__ X, int ldx,
        const float* __restrict__ bias,
        float* __restrict__ out, long long ostride,
        int M, int Kchunk)
{
    __shared__ float w_sm[2][BK*WSTR];
    __shared__ float x_sm[2][BK*32];

    const int tid = threadIdx.x;
    const int m0  = blockIdx.x * 128;
    const int b0  = blockIdx.y * 32;
    const int kz  = blockIdx.z;
    const int kbase = kz * Kchunk;

    const int ty = tid >> 3;
    const int tx = tid & 7;
    const int r0 = ty * 8;
    const int c0 = tx * 4;

    const int lr = tid >> 2;
    const int lk = (tid & 3) * 4;
    const int xk = tid >> 3;
    const int xc = (tid & 7) * 4;

    unsigned long long acc[4][4];
#pragma unroll
    for (int i = 0; i < 4; i++)
#pragma unroll
        for (int j = 0; j < 4; j++) acc[i][j] = 0ULL;

    float4 wreg[4];
    float4 xreg;

    const int ntiles = Kchunk / BK;

    {
        int k0 = kbase;
        const float* Wb; int ld;
        if (k0 < K1) { Wb = W1 + k0; ld = ldw1; } else { Wb = W2 + (k0 - K1); ld = ldw2; }
#pragma unroll
        for (int i = 0; i < 4; i++)
            wreg[i] = *reinterpret_cast<const float4*>(Wb + (size_t)(m0 + lr + i * 32) * ld + lk);
        xreg = *reinterpret_cast<const float4*>(X + (size_t)(k0 + xk) * ldx + b0 + xc);
    }
    {
#pragma unroll
        for (int i = 0; i < 4; i++) {
            int r = lr + i * 32;
            w_sm[0][(lk + 0) * WSTR + r] = wreg[i].x;
            w_sm[0][(lk + 1) * WSTR + r] = wreg[i].y;
            w_sm[0][(lk + 2) * WSTR + r] = wreg[i].z;
            w_sm[0][(lk + 3) * WSTR + r] = wreg[i].w;
        }
        *reinterpret_cast<float4*>(&x_sm[0][xk * 32 + xc]) = xreg;
    }
    __syncthreads();

    for (int t = 0; t < ntiles; t++) {
        if (t + 1 < ntiles) {
            int k0 = kbase + (t + 1) * BK;
            const float* Wb; int ld;
            if (k0 < K1) { Wb = W1 + k0; ld = ldw1; } else { Wb = W2 + (k0 - K1); ld = ldw2; }
#pragma unroll
            for (int i = 0; i < 4; i++)
                wreg[i] = *reinterpret_cast<const float4*>(Wb + (size_t)(m0 + lr + i * 32) * ld + lk);
            xreg = *reinterpret_cast<const float4*>(X + (size_t)(k0 + xk) * ldx + b0 + xc);
        }

        {
            const float* wb = w_sm[t & 1];
            const float* xb = x_sm[t & 1];
#pragma unroll
            for (int kk = 0; kk < BK; kk++) {
                const float* wr = wb + kk * WSTR + r0;
                ulonglong2 wa  = *reinterpret_cast<const ulonglong2*>(wr);
                ulonglong2 wbv = *reinterpret_cast<const ulonglong2*>(wr + 4);
                float4 xv = *reinterpret_cast<const float4*>(xb + kk * 32 + c0);
                unsigned long long xx0 = pack2(xv.x, xv.x);
                unsigned long long xx1 = pack2(xv.y, xv.y);
                unsigned long long xx2 = pack2(xv.z, xv.z);
                unsigned long long xx3 = pack2(xv.w, xv.w);
                ffma2(acc[0][0], wa.x, xx0);  ffma2(acc[0][1], wa.x, xx1);
                ffma2(acc[0][2], wa.x, xx2);  ffma2(acc[0][3], wa.x, xx3);
                ffma2(acc[1][0], wa.y, xx0);  ffma2(acc[1][1], wa.y, xx1);
                ffma2(acc[1][2], wa.y, xx2);  ffma2(acc[1][3], wa.y, xx3);
                ffma2(acc[2][0], wbv.x, xx0); ffma2(acc[2][1], wbv.x, xx1);
                ffma2(acc[2][2], wbv.x, xx2); ffma2(acc[2][3], wbv.x, xx3);
                ffma2(acc[3][0], wbv.y, xx0); ffma2(acc[3][1], wbv.y, xx1);
                ffma2(acc[3][2], wbv.y, xx2); ffma2(acc[3][3], wbv.y, xx3);
            }
        }

        if (t + 1 < ntiles) {
            int buf = (t + 1) & 1;
#pragma unroll
            for (int i = 0; i < 4; i++) {
                int r = lr + i * 32;
                w_sm[buf][(lk + 0) * WSTR + r] = wreg[i].x;
                w_sm[buf][(lk + 1) * WSTR + r] = wreg[i].y;
                w_sm[buf][(lk + 2) * WSTR + r] = wreg[i].z;
                w_sm[buf][(lk + 3) * WSTR + r] = wreg[i].w;
            }
            *reinterpret_cast<float4*>(&x_sm[buf][xk * 32 + xc]) = xreg;
        }
        __syncthreads();
    }

    if (MODE == 1 || MODE == 4) {
        // stage C tile [col][m] into smem, then coalesced 128B stores per col
        float* c = &w_sm[0][0];
#pragma unroll
        for (int rp = 0; rp < 4; rp++) {
            int m = r0 + rp * 2;
            float bv0 = bias[m0 + m], bv1 = bias[m0 + m + 1];
#pragma unroll
            for (int cj = 0; cj < 4; cj++) {
                float2 v = unpack2(acc[rp][cj]);
                int col = c0 + cj;
                c[col * 132 + m]     = v.x + bv0;
                c[col * 132 + m + 1] = v.y + bv1;
            }
        }
        __syncthreads();
        int col = tid >> 2, seg = (tid & 3) * 32;
        int cg = b0 + col;
        float* op;
        if (MODE == 1) op = out + (size_t)cg * ostride + m0 + seg;
        else           op = out + ((size_t)(cg & 31) * TT + (cg >> 5)) * VV + m0 + seg;
        const float* cp = c + col * 132 + seg;
#pragma unroll
        for (int i = 0; i < 8; i++)
            *reinterpret_cast<float4*>(op + i * 4) =
                *reinterpret_cast<const float4*>(cp + i * 4);
    } else if (MODE == 2) {
        float* p = out + (size_t)kz * M * 32;
#pragma unroll
        for (int rp = 0; rp < 4; rp++) {
            int m = m0 + r0 + rp * 2;
#pragma unroll
            for (int cj = 0; cj < 4; cj++) {
                float2 v = unpack2(acc[rp][cj]);
                int col = c0 + cj;
                p[(size_t)m * 32 + col]       = v.x;
                p[(size_t)(m + 1) * 32 + col] = v.y;
            }
        }
    } else {  // MODE 3: x-precompute, col = t*32+b -> out[t][m][b]
#pragma unroll
        for (int rp = 0; rp < 4; rp++) {
            int m = m0 + r0 + rp * 2;
#pragma unroll
            for (int cj = 0; cj < 4; cj++) {
                float2 v = unpack2(acc[rp][cj]);
                int cg = b0 + c0 + cj;
                float* p = out + (size_t)(cg >> 5) * M * 32 + (cg & 31);
                p[(size_t)m * 32]       = v.x;
                p[(size_t)(m + 1) * 32] = v.y;
            }
        }
    }
}

// ---------------------------------------------------------------------------
// target dtype detection
// ---------------------------------------------------------------------------
__global__ void detect_k(const int* __restrict__ tgt) {
    __shared__ int anynz;
    if (threadIdx.x == 0) anynz = 0;
    __syncthreads();
    int local = 0;
    for (int i = threadIdx.x * 2 + 1; i < BB * TT; i += 512)
        if (tgt[i] != 0) local = 1;
    if (local) atomicOr(&anynz, 1);
    __syncthreads();
    if (threadIdx.x == 0) g_is64 = (anynz == 0) ? 1 : 0;
}

// ---------------------------------------------------------------------------
// init
// ---------------------------------------------------------------------------
__global__ void init_k(const float* __restrict__ ench,
                       const float* __restrict__ bih,
                       const float* __restrict__ bhh) {
    int idx = blockIdx.x * 256 + threadIdx.x;   // 32768
    int j = idx >> 5, b = idx & 31;
    float h = ench[b * HH + j];
    g_hT[idx] = h;
    g_cT[idx] = 0.f;
    g_Xg[HH * BB + idx] = h;                    // h-part of gates input
    if (idx < 4 * HH) g_bsum[idx] = bih[idx] + bhh[idx];
}

// ---------------------------------------------------------------------------
// transpose encoder_outputs [1312][1024] -> encT [1024][1312]
// ---------------------------------------------------------------------------
__global__ void transpose_enc(const float* __restrict__ enc) {
    __shared__ float tile[32][33];
    int bs0 = blockIdx.x * 32, h0 = blockIdx.y * 32;
    int x = threadIdx.x, y = threadIdx.y;
#pragma unroll
    for (int i = 0; i < 32; i += 8)
        tile[y + i][x] = enc[(size_t)(bs0 + y + i) * HH + h0 + x];
    __syncthreads();
#pragma unroll
    for (int i = 0; i < 32; i += 8)
        g_encT[(size_t)(h0 + y + i) * BS + bs0 + x] = tile[x][y + i];
}

// ---------------------------------------------------------------------------
// embed all teacher-forced tokens: Xall[j][t*32+b] = emb[token(t,b)][j]
// grid = TT blocks, 256 threads
// ---------------------------------------------------------------------------
__global__ void __launch_bounds__(256)
embed_all(const float* __restrict__ emb, const void* __restrict__ tgt) {
    __shared__ int toks[32];
    __shared__ float tile[32][33];
    const int t = blockIdx.x;
    const int tid = threadIdx.x;

    if (tid < 32) {
        long long tok;
        if (t == 0) tok = 0;
        else if (g_is64) tok = ((const long long*)tgt)[(size_t)tid * TT + (t - 1)];
        else             tok = (long long)((const int*)tgt)[(size_t)tid * TT + (t - 1)];
        toks[tid] = (int)tok;
    }
    __syncthreads();

    for (int j0 = 0; j0 < HH; j0 += 32) {
        for (int idx = tid; idx < 1024; idx += 256) {
            int b = idx >> 5, j = idx & 31;
            tile[b][j] = emb[(size_t)toks[b] * HH + j0 + j];
        }
        __syncthreads();
        for (int idx = tid; idx < 1024; idx += 256) {
            int j = idx >> 5, b = idx & 31;
            g_Xall[(size_t)(j0 + j) * BS + t * 32 + b] = tile[b][j];
        }
        __syncthreads();
    }
}

// ---------------------------------------------------------------------------
// Attention + q-partial combine. One block per batch b.
// ---------------------------------------------------------------------------
__global__ void __launch_bounds__(256)
attn_step(const float* __restrict__ Vw, const float* __restrict__ bVp,
          const float* __restrict__ bq,
          const float* __restrict__ enc, float* __restrict__ out_attn, int t)
{
    __shared__ float qs[HH];
    __shared__ float vws[HH];
    __shared__ float sc[SS];
    __shared__ float wts[SS];

    const int b = blockIdx.x;
    const int tid = threadIdx.x;
    const int warp = tid >> 5, lane = tid & 31;

    for (int i = tid; i < HH; i += 256) {
        float q = bq[i];
#pragma unroll
        for (int s = 0; s < NSPL; s++) q += g_qp[s * (HH * BB) + i * 32 + b];
        qs[i]  = q;
        vws[i] = Vw[i];
    }
    __syncthreads();

    const float bVv = bVp[0];
    for (int s = warp; s < SS; s += 8) {
        const float* kp = g_keysp + ((size_t)b * SS + s) * HH;
        float acc = 0.f;
        for (int h = lane; h < HH; h += 32)
            acc += tanhf(qs[h] + kp[h]) * vws[h];
#pragma unroll
        for (int o = 16; o; o >>= 1) acc += __shfl_xor_sync(0xffffffffu, acc, o);
        if (lane == 0) sc[s] = acc + bVv;
    }
    __syncthreads();

    if (warp == 0) {
        float v0 = (lane < SS) ? sc[lane] : -3.4e38f;
        float v1 = (lane + 32 < SS) ? sc[lane + 32] : -3.4e38f;
        float m = fmaxf(v0, v1);
#pragma unroll
        for (int o = 16; o; o >>= 1) m = fmaxf(m, __shfl_xor_sync(0xffffffffu, m, o));
        float e0 = (lane < SS) ? expf(v0 - m) : 0.f;
        float e1 = (lane + 32 < SS) ? expf(v1 - m) : 0.f;
        float s = e0 + e1;
#pragma unroll
        for (int o = 16; o; o >>= 1) s += __shfl_xor_sync(0xffffffffu, s, o);
        float inv = 1.f / s;
        size_t abase = ((size_t)b * TT + t) * SS;
        if (lane < SS)      { wts[lane]      = e0 * inv; out_attn[abase + lane]      = e0 * inv; }
        if (lane + 32 < SS) { wts[lane + 32] = e1 * inv; out_attn[abase + lane + 32] = e1 * inv; }
    }
    __syncthreads();

    for (int h = tid; h < HH; h += 256) {
        float c = 0.f;
        const float* ep = enc + (size_t)b * SS * HH + h;
#pragma unroll 1
        for (int s = 0; s < SS; s++)
            c += wts[s] * ep[(size_t)s * HH];
        g_Xg[(size_t)h * 32 + b] = c;               // ctx part (rows 0..1023)
    }
}

// ---------------------------------------------------------------------------
// LSTM pointwise: combine 8 gate partials + precomputed x-gates + bias,
// update c/h, write h into hT, Xg h-part, and Hall[t].
// ---------------------------------------------------------------------------
__device__ __forceinline__ float sigm(float x) { return 1.f / (1.f + expf(-x)); }

__global__ void __launch_bounds__(256) lstm_comb(int t) {
    int idx = blockIdx.x * 256 + threadIdx.x;   // 32768 = j*32 + b
    int j = idx >> 5, b = idx & 31;
    const float* gx = g_gx + (size_t)t * (4 * HH * BB);
    float gi = g_bsum[j]          + gx[idx];
    float gf = g_bsum[HH + j]     + gx[1 * HH * BB + idx];
    float gg = g_bsum[2 * HH + j] + gx[2 * HH * BB + idx];
    float go = g_bsum[3 * HH + j] + gx[3 * HH * BB + idx];
#pragma unroll
    for (int s = 0; s < NSPL; s++) {
        const float* p = g_gp + (size_t)s * (4 * HH * BB);
        gi += p[idx];
        gf += p[1 * HH * BB + idx];
        gg += p[2 * HH * BB + idx];
        go += p[3 * HH * BB + idx];
    }
    float ig = sigm(gi), fg = sigm(gf), ggt = tanhf(gg), og = sigm(go);
    float c = fg * g_cT[idx] + ig * ggt;
    float h = og * tanhf(c);
    g_cT[idx] = c;
    g_hT[idx] = h;
    g_Xg[HH * BB + idx] = h;
    g_Hall[(size_t)j * BS + t * 32 + b] = h;
}

// ---------------------------------------------------------------------------
// final h/c transpose into output
// ---------------------------------------------------------------------------
__global__ void final_hc(float* __restrict__ oh, float* __restrict__ oc) {
    int idx = blockIdx.x * 256 + threadIdx.x;
    int b = idx >> 10, j = idx & 1023;
    oh[idx] = g_hT[j * 32 + b];
    oc[idx] = g_cT[j * 32 + b];
}

// ---------------------------------------------------------------------------
// log_softmax in place over each [16384] row
// ---------------------------------------------------------------------------
__global__ void __launch_bounds__(256) logsoftmax_rows(float* __restrict__ out) {
    float* row = out + (size_t)blockIdx.x * VV;
    __shared__ float red1[8];
    __shared__ float red2[8];
    const int tid = threadIdx.x;
    const int warp = tid >> 5, lane = tid & 31;

    float m = -3.4e38f;
    for (int i = tid; i < VV; i += 256) m = fmaxf(m, row[i]);
#pragma unroll
    for (int o = 16; o; o >>= 1) m = fmaxf(m, __shfl_xor_sync(0xffffffffu, m, o));
    if (lane == 0) red1[warp] = m;
    __syncthreads();
    m = red1[0];
#pragma unroll
    for (int i = 1; i < 8; i++) m = fmaxf(m, red1[i]);

    float s = 0.f;
    for (int i = tid; i < VV; i += 256) s += expf(row[i] - m);
#pragma unroll
    for (int o = 16; o; o >>= 1) s += __shfl_xor_sync(0xffffffffu, s, o);
    if (lane == 0) red2[warp] = s;
    __syncthreads();
    s = red2[0];
#pragma unroll
    for (int i = 1; i < 8; i++) s += red2[i];
    float shift = m + logf(s);

    for (int i = tid; i < VV; i += 256) row[i] = row[i] - shift;
}

// ---------------------------------------------------------------------------
// host launcher
// ---------------------------------------------------------------------------
extern "C" void kernel_launch(void* const* d_in, const int* in_sizes, int n_in,
                              void* d_out, int out_size)
{
    const float* enc   = (const float*)d_in[0];
    const float* ench  = (const float*)d_in[1];
    const void*  tgt   = d_in[2];
    const float* emb   = (const float*)d_in[3];
    const float* Wq    = (const float*)d_in[4];
    const float* bq    = (const float*)d_in[5];
    const float* Wk    = (const float*)d_in[6];
    const float* bk    = (const float*)d_in[7];
    const float* Vw    = (const float*)d_in[8];
    const float* bV    = (const float*)d_in[9];
    const float* Wih   = (const float*)d_in[10];
    const float* Whh   = (const float*)d_in[11];
    const float* bih   = (const float*)d_in[12];
    const float* bhh   = (const float*)d_in[13];
    const float* Wout  = (const float*)d_in[14];
    const float* bout  = (const float*)d_in[15];
    float* out = (float*)d_out;

    float *keysp, *encT, *hT, *Xg, *qp, *gp, *Xall, *gx, *Hall;
    cudaGetSymbolAddress((void**)&keysp, g_keysp);
    cudaGetSymbolAddress((void**)&encT,  g_encT);
    cudaGetSymbolAddress((void**)&hT,    g_hT);
    cudaGetSymbolAddress((void**)&Xg,    g_Xg);
    cudaGetSymbolAddress((void**)&qp,    g_qp);
    cudaGetSymbolAddress((void**)&gp,    g_gp);
    cudaGetSymbolAddress((void**)&Xall,  g_Xall);
    cudaGetSymbolAddress((void**)&gx,    g_gx);
    cudaGetSymbolAddress((void**)&Hall,  g_Hall);

    const int BIGK = 1 << 28;

    detect_k<<<1, 256>>>((const int*)tgt);
    init_k<<<128, 256>>>(ench, bih, bhh);
    transpose_enc<<<dim3(BS / 32, HH / 32), dim3(32, 8)>>>(enc);
    embed_all<<<TT, 256>>>(emb, tgt);

    // keys_proj[bs][g] = enc[bs].Wk[g] + bk   (MODE1, N=1312)
    gemm128<1><<<dim3(HH / 128, 41, 1), 128>>>(
        Wk, HH, BIGK, nullptr, 0, encT, BS, bk, keysp, (long long)HH, HH, HH);

    // x-gates precompute: Wih_x[4096,1024] * Xall -> gx[t][m][b]  (MODE3, N=1312)
    gemm128<3><<<dim3(4 * HH / 128, 41, 1), 128>>>(
        Wih, 2 * HH, BIGK, nullptr, 0, Xall, BS, nullptr, gx, 0, 4 * HH, HH);

    for (int t = 0; t < TT; t++) {
        // q partials: Wq[1024,1024] * hT  (split-K 8, Kchunk 128)
        gemm128<2><<<dim3(HH / 128, 1, NSPL), 128>>>(
            Wq, HH, BIGK, nullptr, 0, hT, 32, nullptr, qp, 0, HH, HH / NSPL);

        attn_step<<<BB, 256>>>(Vw, bV, bq, enc, out + OFF_A, t);

        // gate partials: [Wih_ctx | Whh][4096,2048] * [ctx;h]  (split-K 8, Kchunk 256)
        gemm128<2><<<dim3(4 * HH / 128, 1, NSPL), 128>>>(
            Wih + HH, 2 * HH, HH, Whh, HH, Xg, 32, nullptr, gp, 0, 4 * HH, 2 * HH / NSPL);

        lstm_comb<<<128, 256>>>(t);
    }

    // deferred logits: Wout[16384,1024] * Hall[1024,1312] -> out  (MODE4)
    gemm128<4><<<dim3(VV / 128, 41, 1), 128>>>(
        Wout, HH, BIGK, nullptr, 0, Hall, BS, bout, out, 0, VV, HH);

    final_hc<<<128, 256>>>(out + OFF_H, out + OFF_C);
    logsoftmax_rows<<<BB * TT, 256>>>(out);
}